// round 12
// baseline (speedup 1.0000x reference)
#include <cuda_runtime.h>
#include <cstdint>

// Problem constants
#define B 4
#define H 128
#define W 128
#define BINS 64
#define KK 26            // 25 neighbors + current
#define KS 5

// Tiling: 8 x 16 output pixels per CTA, halo 2 -> 12 x 20 staged pixels
#define TH 8
#define TW 16
#define PH (TH + 4)      // 12
#define PW (TW + 4)      // 20
#define NPIX (PH * PW)   // 240 staged pixels
#define AS 132           // attn k-stride in floats (k*AS 16B-aligned)
#define THREADS 512

#define SREF_FLOATS (NPIX * BINS)      // 15360 -> 61440 B (natural [pix][bin])
#define SATTN_FLOATS (KK * AS)         // 3432  -> 13728 B
#define SMEM_BYTES ((SREF_FLOATS + SATTN_FLOATS) * 4)   // 75168 B -> 2 CTAs/SM

__device__ __forceinline__ void cp_async16(uint32_t dst, const void* src, int src_bytes) {
    asm volatile("cp.async.cg.shared.global [%0], [%1], 16, %2;\n"
                 :: "r"(dst), "l"(src), "r"(src_bytes) : "memory");
}

__global__ __launch_bounds__(THREADS, 2)
void agg_kernel(const float* __restrict__ attn,
                const float* __restrict__ refv,
                const float* __restrict__ curv,
                float* __restrict__ out) {
    extern __shared__ float smem[];
    float* s_ref  = smem;                 // [pix][64 bins], pix = lr*PW + lc
    float* s_attn = smem + SREF_FLOATS;   // [k][pix], pix = r*TW + c

    const int tid  = threadIdx.x;
    const int bidx = blockIdx.x;          // 512 blocks: 8 tw x 16 th x 4 batch
    const int tw = bidx & 7;
    const int th = (bidx >> 3) & 15;
    const int b  = bidx >> 7;
    const int h0 = th * TH;
    const int w0 = tw * TW;

    const float* refb = refv + (size_t)b * H * W * BINS;
    const uint32_t s_ref_b = (uint32_t)__cvta_generic_to_shared(s_ref);

    // ---------- Stage ref tile+halo via cp.async (natural layout) ----------
    // 240 pixels * 16 float4 = 3840 chunks; 512 threads -> 7 full + 1 half iter.
    #pragma unroll
    for (int i = 0; i < 8; ++i) {
        int idx = tid + i * THREADS;
        if (idx < NPIX * 16) {
            int g   = idx & 15;
            int pix = idx >> 4;
            int lr  = pix / PW;
            int lc  = pix - lr * PW;
            int gh  = h0 + lr - 2;
            int gw  = w0 + lc - 2;
            bool ok = ((unsigned)gh < (unsigned)H) && ((unsigned)gw < (unsigned)W);
            const float* src = refb + (((ok ? gh : 0) * W + (ok ? gw : 0)) * BINS + g * 4);
            uint32_t dst = s_ref_b + (uint32_t)((pix * BINS + g * 4) * 4);
            cp_async16(dst, src, ok ? 16 : 0);   // zero-fill halo
        }
    }
    asm volatile("cp.async.commit_group;\n" ::: "memory");

    // ---------- Stage attn tile, transposed [k][pix] ----------
    // 8*16*26 = 3328 elements; strided loop.
    #pragma unroll 1
    for (int idx = tid; idx < TH * TW * KK; idx += THREADS) {
        int pix = idx / KK;
        int k   = idx - pix * KK;
        int rr  = pix >> 4;
        int cc  = pix & 15;
        float a = attn[(((b * H + h0 + rr) * W) + (w0 + cc)) * KK + k];
        s_attn[k * AS + pix] = a;
    }

    asm volatile("cp.async.wait_group 0;\n" ::: "memory");
    __syncthreads();

    // ---------- Compute: thread = 1 row x 4 px x 4 bins ----------
    const int bg = tid & 15;             // bin float4-group 0..15
    const int c0 = ((tid >> 4) & 3) * 4; // first output col: 0,4,8,12
    const int r  = tid >> 6;             // output row 0..7

    float4 acc[4];
    #pragma unroll
    for (int p = 0; p < 4; ++p) acc[p] = make_float4(0.f, 0.f, 0.f, 0.f);

    const float* arow = s_attn + r * TW + c0;

    #pragma unroll
    for (int di = 0; di < 5; ++di) {
        // 8-wide window (4 outputs + 4 halo) of staged row (r+di)
        const float* vrow = s_ref + ((r + di) * PW + c0) * BINS + bg * 4;
        float4 v[8];
        #pragma unroll
        for (int j = 0; j < 8; ++j)
            v[j] = *reinterpret_cast<const float4*>(vrow + j * BINS);

        #pragma unroll
        for (int dj = 0; dj < 5; ++dj) {
            // one broadcast LDS.128: attn for this tap, 4 adjacent pixels
            float4 a = *reinterpret_cast<const float4*>(arow + (di * KS + dj) * AS);
            acc[0].x = fmaf(a.x, v[0 + dj].x, acc[0].x);
            acc[0].y = fmaf(a.x, v[0 + dj].y, acc[0].y);
            acc[0].z = fmaf(a.x, v[0 + dj].z, acc[0].z);
            acc[0].w = fmaf(a.x, v[0 + dj].w, acc[0].w);
            acc[1].x = fmaf(a.y, v[1 + dj].x, acc[1].x);
            acc[1].y = fmaf(a.y, v[1 + dj].y, acc[1].y);
            acc[1].z = fmaf(a.y, v[1 + dj].z, acc[1].z);
            acc[1].w = fmaf(a.y, v[1 + dj].w, acc[1].w);
            acc[2].x = fmaf(a.z, v[2 + dj].x, acc[2].x);
            acc[2].y = fmaf(a.z, v[2 + dj].y, acc[2].y);
            acc[2].z = fmaf(a.z, v[2 + dj].z, acc[2].z);
            acc[2].w = fmaf(a.z, v[2 + dj].w, acc[2].w);
            acc[3].x = fmaf(a.w, v[3 + dj].x, acc[3].x);
            acc[3].y = fmaf(a.w, v[3 + dj].y, acc[3].y);
            acc[3].z = fmaf(a.w, v[3 + dj].z, acc[3].z);
            acc[3].w = fmaf(a.w, v[3 + dj].w, acc[3].w);
        }
    }

    // ---------- Epilogue: += attn[25]*current, direct coalesced float4 ----------
    const float* curb = curv + (size_t)b * H * W * BINS;
    float*       outb = out  + (size_t)b * H * W * BINS;
    float4 a25 = *reinterpret_cast<const float4*>(arow + 25 * AS);
    const float* ap = &a25.x;
    #pragma unroll
    for (int p = 0; p < 4; ++p) {
        int gaddr = ((h0 + r) * W + (w0 + c0 + p)) * BINS + bg * 4;
        float4 cv = *reinterpret_cast<const float4*>(curb + gaddr);
        float av = ap[p];
        float4 o;
        o.x = fmaf(av, cv.x, acc[p].x);
        o.y = fmaf(av, cv.y, acc[p].y);
        o.z = fmaf(av, cv.z, acc[p].z);
        o.w = fmaf(av, cv.w, acc[p].w);
        *reinterpret_cast<float4*>(outb + gaddr) = o;
    }
}

extern "C" void kernel_launch(void* const* d_in, const int* in_sizes, int n_in,
                              void* d_out, int out_size) {
    const float* attn = (const float*)d_in[0];   // [4,128,128,26]
    const float* refv = (const float*)d_in[1];   // [4,128,128,64]
    const float* curv = (const float*)d_in[2];   // [4,128,128,64]
    float* out = (float*)d_out;                  // [4,128,128,64]

    cudaFuncSetAttribute(agg_kernel, cudaFuncAttributeMaxDynamicSharedMemorySize,
                         SMEM_BYTES);

    const int nblocks = B * (H / TH) * (W / TW);   // 4*16*8 = 512
    agg_kernel<<<nblocks, THREADS, SMEM_BYTES>>>(attn, refv, curv, out);
}

// round 13
// speedup vs baseline: 1.1045x; 1.1045x over previous
#include <cuda_runtime.h>
#include <cstdint>

// Problem constants
#define B 4
#define H 128
#define W 128
#define BINS 64
#define KK 26            // 25 neighbors + current
#define KS 5

// Tiling: 8 x 8 output pixels per CTA, halo 2 -> 12 x 12 staged pixels
#define TH 8
#define TW 8
#define PH (TH + 4)      // 12
#define PW (TW + 4)      // 12
#define NPIX (PH * PW)   // 144 staged pixels
#define AS 68            // attn k-stride in floats (>=64, k*AS 16B-aligned)
#define THREADS 128

#define SREF_FLOATS (NPIX * BINS)      // 9216 -> 36864 B (natural [pix][bin])
#define SATTN_FLOATS (KK * AS)         // 1768 -> 7072 B
#define SMEM_BYTES ((SREF_FLOATS + SATTN_FLOATS) * 4)   // 43936 B -> 5 CTAs/SM

__device__ __forceinline__ void cp_async16(uint32_t dst, const void* src, int src_bytes) {
    asm volatile("cp.async.cg.shared.global [%0], [%1], 16, %2;\n"
                 :: "r"(dst), "l"(src), "r"(src_bytes) : "memory");
}

__global__ __launch_bounds__(THREADS, 5)
void agg_kernel(const float* __restrict__ attn,
                const float* __restrict__ refv,
                const float* __restrict__ curv,
                float* __restrict__ out) {
    extern __shared__ float smem[];
    float* s_ref  = smem;                 // [pix][64 bins], pix = lr*PW + lc
    float* s_attn = smem + SREF_FLOATS;   // [k][pix], pix = r*TW + c

    const int tid  = threadIdx.x;
    const int bidx = blockIdx.x;          // 1024 blocks: 16 tw x 16 th x 4 batch
    const int tw = bidx & 15;
    const int th = (bidx >> 4) & 15;
    const int b  = bidx >> 8;
    const int h0 = th * TH;
    const int w0 = tw * TW;

    const float* refb = refv + (size_t)b * H * W * BINS;
    const uint32_t s_ref_b = (uint32_t)__cvta_generic_to_shared(s_ref);

    // ---------- Stage ref tile+halo via cp.async (natural layout) ----------
    // 144 pixels * 16 float4 = 2304 chunks = 18 per thread exactly.
    #pragma unroll
    for (int i = 0; i < (NPIX * 16) / THREADS; ++i) {
        int idx = tid + i * THREADS;
        int g   = idx & 15;
        int pix = idx >> 4;
        int lr  = pix / PW;
        int lc  = pix - lr * PW;
        int gh  = h0 + lr - 2;
        int gw  = w0 + lc - 2;
        bool ok = ((unsigned)gh < (unsigned)H) && ((unsigned)gw < (unsigned)W);
        const float* src = refb + (((ok ? gh : 0) * W + (ok ? gw : 0)) * BINS + g * 4);
        uint32_t dst = s_ref_b + (uint32_t)((pix * BINS + g * 4) * 4);
        cp_async16(dst, src, ok ? 16 : 0);   // zero-fill halo
    }
    asm volatile("cp.async.commit_group;\n" ::: "memory");

    // ---------- Stage attn tile, transposed [k][pix] ----------
    // 8*8*26 = 1664 elements = 13 per thread exactly.
    #pragma unroll 1
    for (int idx = tid; idx < TH * TW * KK; idx += THREADS) {
        int pix = idx / KK;
        int k   = idx - pix * KK;
        int rr  = pix >> 3;
        int cc  = pix & 7;
        float a = attn[(((b * H + h0 + rr) * W) + (w0 + cc)) * KK + k];
        s_attn[k * AS + pix] = a;
    }

    asm volatile("cp.async.wait_group 0;\n" ::: "memory");
    __syncthreads();

    // ---------- Compute: thread = 2 rows x 4 px x 4 bins (R7 body) ----------
    const int bg = tid & 15;             // float4 bin group 0..15
    const int pg = tid >> 4;             // 0..7
    const int r0 = (pg >> 1) * 2;        // first output row: 0,2,4,6
    const int c0 = (pg & 1) * 4;         // first output col: 0,4

    float4 acc0[4], acc1[4];
    #pragma unroll
    for (int p = 0; p < 4; ++p) {
        acc0[p] = make_float4(0.f, 0.f, 0.f, 0.f);
        acc1[p] = make_float4(0.f, 0.f, 0.f, 0.f);
    }

    const float* arow0 = s_attn + r0 * TW + c0;   // attn base, output row r0
    const float* arow1 = arow0 + TW;              // output row r0+1

    // Staged rows r0 .. r0+5: row (r0+arl) serves out-row r0 (di=arl, arl<=4)
    // and out-row r0+1 (di=arl-1, arl>=1) -> 2x vertical reuse of v window.
    #pragma unroll
    for (int arl = 0; arl < 6; ++arl) {
        const float* vrow = s_ref + ((r0 + arl) * PW + c0) * BINS + bg * 4;
        float4 v[8];
        #pragma unroll
        for (int j = 0; j < 8; ++j)
            v[j] = *reinterpret_cast<const float4*>(vrow + j * BINS);

        #pragma unroll
        for (int dj = 0; dj < 5; ++dj) {
            if (arl <= 4) {   // compile-time pruned
                float4 a = *reinterpret_cast<const float4*>(arow0 + (arl * KS + dj) * AS);
                acc0[0].x = fmaf(a.x, v[0 + dj].x, acc0[0].x);
                acc0[0].y = fmaf(a.x, v[0 + dj].y, acc0[0].y);
                acc0[0].z = fmaf(a.x, v[0 + dj].z, acc0[0].z);
                acc0[0].w = fmaf(a.x, v[0 + dj].w, acc0[0].w);
                acc0[1].x = fmaf(a.y, v[1 + dj].x, acc0[1].x);
                acc0[1].y = fmaf(a.y, v[1 + dj].y, acc0[1].y);
                acc0[1].z = fmaf(a.y, v[1 + dj].z, acc0[1].z);
                acc0[1].w = fmaf(a.y, v[1 + dj].w, acc0[1].w);
                acc0[2].x = fmaf(a.z, v[2 + dj].x, acc0[2].x);
                acc0[2].y = fmaf(a.z, v[2 + dj].y, acc0[2].y);
                acc0[2].z = fmaf(a.z, v[2 + dj].z, acc0[2].z);
                acc0[2].w = fmaf(a.z, v[2 + dj].w, acc0[2].w);
                acc0[3].x = fmaf(a.w, v[3 + dj].x, acc0[3].x);
                acc0[3].y = fmaf(a.w, v[3 + dj].y, acc0[3].y);
                acc0[3].z = fmaf(a.w, v[3 + dj].z, acc0[3].z);
                acc0[3].w = fmaf(a.w, v[3 + dj].w, acc0[3].w);
            }
            if (arl >= 1) {   // compile-time pruned
                float4 a = *reinterpret_cast<const float4*>(arow1 + ((arl - 1) * KS + dj) * AS);
                acc1[0].x = fmaf(a.x, v[0 + dj].x, acc1[0].x);
                acc1[0].y = fmaf(a.x, v[0 + dj].y, acc1[0].y);
                acc1[0].z = fmaf(a.x, v[0 + dj].z, acc1[0].z);
                acc1[0].w = fmaf(a.x, v[0 + dj].w, acc1[0].w);
                acc1[1].x = fmaf(a.y, v[1 + dj].x, acc1[1].x);
                acc1[1].y = fmaf(a.y, v[1 + dj].y, acc1[1].y);
                acc1[1].z = fmaf(a.y, v[1 + dj].z, acc1[1].z);
                acc1[1].w = fmaf(a.y, v[1 + dj].w, acc1[1].w);
                acc1[2].x = fmaf(a.z, v[2 + dj].x, acc1[2].x);
                acc1[2].y = fmaf(a.z, v[2 + dj].y, acc1[2].y);
                acc1[2].z = fmaf(a.z, v[2 + dj].z, acc1[2].z);
                acc1[2].w = fmaf(a.z, v[2 + dj].w, acc1[2].w);
                acc1[3].x = fmaf(a.w, v[3 + dj].x, acc1[3].x);
                acc1[3].y = fmaf(a.w, v[3 + dj].y, acc1[3].y);
                acc1[3].z = fmaf(a.w, v[3 + dj].z, acc1[3].z);
                acc1[3].w = fmaf(a.w, v[3 + dj].w, acc1[3].w);
            }
        }
    }

    // ---------- Epilogue: += attn[25]*current, direct coalesced float4 ----------
    const float* curb = curv + (size_t)b * H * W * BINS;
    float*       outb = out  + (size_t)b * H * W * BINS;
    #pragma unroll
    for (int rr = 0; rr < 2; ++rr) {
        float4 a25 = *reinterpret_cast<const float4*>(
            s_attn + 25 * AS + (r0 + rr) * TW + c0);
        const float* ap = &a25.x;
        float4* accp = (rr == 0) ? acc0 : acc1;
        #pragma unroll
        for (int p = 0; p < 4; ++p) {
            int gaddr = ((h0 + r0 + rr) * W + (w0 + c0 + p)) * BINS + bg * 4;
            float4 cv = *reinterpret_cast<const float4*>(curb + gaddr);
            float a = ap[p];
            float4 o;
            o.x = fmaf(a, cv.x, accp[p].x);
            o.y = fmaf(a, cv.y, accp[p].y);
            o.z = fmaf(a, cv.z, accp[p].z);
            o.w = fmaf(a, cv.w, accp[p].w);
            *reinterpret_cast<float4*>(outb + gaddr) = o;
        }
    }
}

extern "C" void kernel_launch(void* const* d_in, const int* in_sizes, int n_in,
                              void* d_out, int out_size) {
    const float* attn = (const float*)d_in[0];   // [4,128,128,26]
    const float* refv = (const float*)d_in[1];   // [4,128,128,64]
    const float* curv = (const float*)d_in[2];   // [4,128,128,64]
    float* out = (float*)d_out;                  // [4,128,128,64]

    cudaFuncSetAttribute(agg_kernel, cudaFuncAttributeMaxDynamicSharedMemorySize,
                         SMEM_BYTES);

    const int nblocks = B * (H / TH) * (W / TW);   // 4*16*16 = 1024
    agg_kernel<<<nblocks, THREADS, SMEM_BYTES>>>(attn, refv, curv, out);
}

// round 14
// speedup vs baseline: 1.2569x; 1.1380x over previous
#include <cuda_runtime.h>
#include <cstdint>

// Problem constants
#define B 4
#define H 128
#define W 128
#define BINS 64
#define KK 26            // 25 neighbors + current
#define KS 5

// Tiling: 8 x 16 output pixels per CTA, halo 2 -> 12 x 20 staged pixels
#define TH 8
#define TW 16
#define PH (TH + 4)      // 12
#define PW (TW + 4)      // 20
#define NPIX (PH * PW)   // 240 staged pixels
#define AS 132           // attn k-stride in floats (k*AS 16B-aligned)
#define THREADS 256

#define SREF_FLOATS (NPIX * BINS)      // 15360 -> 61440 B (natural [pix][bin])
#define SATTN_FLOATS (KK * AS)         // 3432  -> 13728 B
#define SMEM_BYTES ((SREF_FLOATS + SATTN_FLOATS) * 4)   // 75168 B -> 3 CTAs/SM

__device__ __forceinline__ void cp_async16(uint32_t dst, const void* src, int src_bytes) {
    asm volatile("cp.async.cg.shared.global [%0], [%1], 16, %2;\n"
                 :: "r"(dst), "l"(src), "r"(src_bytes) : "memory");
}

__global__ __launch_bounds__(THREADS, 3)
void agg_kernel(const float* __restrict__ attn,
                const float* __restrict__ refv,
                const float* __restrict__ curv,
                float* __restrict__ out) {
    extern __shared__ float smem[];
    float* s_ref  = smem;                 // [pix][64 bins], pix = lr*PW + lc
    float* s_attn = smem + SREF_FLOATS;   // [k][pix], pix = r*TW + c

    const int tid  = threadIdx.x;
    const int bidx = blockIdx.x;          // 512 blocks: 8 tw x 16 th x 4 batch
    const int tw = bidx & 7;
    const int th = (bidx >> 3) & 15;
    const int b  = bidx >> 7;
    const int h0 = th * TH;
    const int w0 = tw * TW;

    const float* refb = refv + (size_t)b * H * W * BINS;
    const uint32_t s_ref_b = (uint32_t)__cvta_generic_to_shared(s_ref);

    // ---------- Stage ref tile+halo via cp.async (natural layout) ----------
    // 240 pixels * 16 float4 = 3840 chunks = 15 per thread exactly.
    #pragma unroll
    for (int i = 0; i < (NPIX * 16) / THREADS; ++i) {
        int idx = tid + i * THREADS;
        int g   = idx & 15;
        int pix = idx >> 4;
        int lr  = pix / PW;
        int lc  = pix - lr * PW;
        int gh  = h0 + lr - 2;
        int gw  = w0 + lc - 2;
        bool ok = ((unsigned)gh < (unsigned)H) && ((unsigned)gw < (unsigned)W);
        const float* src = refb + (((ok ? gh : 0) * W + (ok ? gw : 0)) * BINS + g * 4);
        uint32_t dst = s_ref_b + (uint32_t)((pix * BINS + g * 4) * 4);
        cp_async16(dst, src, ok ? 16 : 0);   // zero-fill halo
    }
    asm volatile("cp.async.commit_group;\n" ::: "memory");

    // ---------- Stage attn, transposed [k][pix], division-free walker ----------
    {
        int pix = tid / KK;
        int k   = tid - pix * KK;
        #pragma unroll
        for (int i = 0; i < 13; ++i) {   // 3328 = 13*256 exactly
            int rr = pix >> 4, cc = pix & 15;
            float a = attn[(((b * H + h0 + rr) * W) + (w0 + cc)) * KK + k];
            s_attn[k * AS + pix] = a;
            k += 22; pix += 9;
            if (k >= KK) { k -= KK; pix += 1; }
        }
    }

    asm volatile("cp.async.wait_group 0;\n" ::: "memory");
    __syncthreads();

    // ---------- Compute: thread = 2 rows x 4 px x 4 bins (R7 body) ----------
    const int bg = tid & 15;             // float4 bin group 0..15
    const int pg = tid >> 4;             // 0..15
    const int r0 = (pg >> 2) * 2;        // first output row: 0,2,4,6
    const int c0 = (pg & 3) * 4;         // first output col: 0,4,8,12

    float4 acc0[4], acc1[4];
    #pragma unroll
    for (int p = 0; p < 4; ++p) {
        acc0[p] = make_float4(0.f, 0.f, 0.f, 0.f);
        acc1[p] = make_float4(0.f, 0.f, 0.f, 0.f);
    }

    const float* arow0 = s_attn + r0 * TW + c0;   // attn base, output row r0
    const float* arow1 = arow0 + TW;              // output row r0+1

    // Staged rows r0 .. r0+5: row (r0+arl) serves out-row r0 (di=arl, arl<=4)
    // and out-row r0+1 (di=arl-1, arl>=1) -> 2x vertical reuse of v window.
    // Rolling 5-slot window: col j lives in slot j%5; prefetch 4 cols ahead.
    #pragma unroll
    for (int arl = 0; arl < 6; ++arl) {
        const float* vrow = s_ref + ((r0 + arl) * PW + c0) * BINS + bg * 4;
        float4 v[5];
        #pragma unroll
        for (int j = 0; j < 4; ++j)
            v[j] = *reinterpret_cast<const float4*>(vrow + j * BINS);

        #pragma unroll
        for (int dj = 0; dj < 5; ++dj) {
            if (dj < 4)   // prefetch col dj+4 into dead slot; used 4 iters later
                v[(dj + 4) % 5] = *reinterpret_cast<const float4*>(vrow + (dj + 4) * BINS);
            if (arl <= 4) {   // compile-time pruned
                float4 a = *reinterpret_cast<const float4*>(arow0 + (arl * KS + dj) * AS);
                acc0[0].x = fmaf(a.x, v[(0 + dj) % 5].x, acc0[0].x);
                acc0[0].y = fmaf(a.x, v[(0 + dj) % 5].y, acc0[0].y);
                acc0[0].z = fmaf(a.x, v[(0 + dj) % 5].z, acc0[0].z);
                acc0[0].w = fmaf(a.x, v[(0 + dj) % 5].w, acc0[0].w);
                acc0[1].x = fmaf(a.y, v[(1 + dj) % 5].x, acc0[1].x);
                acc0[1].y = fmaf(a.y, v[(1 + dj) % 5].y, acc0[1].y);
                acc0[1].z = fmaf(a.y, v[(1 + dj) % 5].z, acc0[1].z);
                acc0[1].w = fmaf(a.y, v[(1 + dj) % 5].w, acc0[1].w);
                acc0[2].x = fmaf(a.z, v[(2 + dj) % 5].x, acc0[2].x);
                acc0[2].y = fmaf(a.z, v[(2 + dj) % 5].y, acc0[2].y);
                acc0[2].z = fmaf(a.z, v[(2 + dj) % 5].z, acc0[2].z);
                acc0[2].w = fmaf(a.z, v[(2 + dj) % 5].w, acc0[2].w);
                acc0[3].x = fmaf(a.w, v[(3 + dj) % 5].x, acc0[3].x);
                acc0[3].y = fmaf(a.w, v[(3 + dj) % 5].y, acc0[3].y);
                acc0[3].z = fmaf(a.w, v[(3 + dj) % 5].z, acc0[3].z);
                acc0[3].w = fmaf(a.w, v[(3 + dj) % 5].w, acc0[3].w);
            }
            if (arl >= 1) {   // compile-time pruned
                float4 a = *reinterpret_cast<const float4*>(arow1 + ((arl - 1) * KS + dj) * AS);
                acc1[0].x = fmaf(a.x, v[(0 + dj) % 5].x, acc1[0].x);
                acc1[0].y = fmaf(a.x, v[(0 + dj) % 5].y, acc1[0].y);
                acc1[0].z = fmaf(a.x, v[(0 + dj) % 5].z, acc1[0].z);
                acc1[0].w = fmaf(a.x, v[(0 + dj) % 5].w, acc1[0].w);
                acc1[1].x = fmaf(a.y, v[(1 + dj) % 5].x, acc1[1].x);
                acc1[1].y = fmaf(a.y, v[(1 + dj) % 5].y, acc1[1].y);
                acc1[1].z = fmaf(a.y, v[(1 + dj) % 5].z, acc1[1].z);
                acc1[1].w = fmaf(a.y, v[(1 + dj) % 5].w, acc1[1].w);
                acc1[2].x = fmaf(a.z, v[(2 + dj) % 5].x, acc1[2].x);
                acc1[2].y = fmaf(a.z, v[(2 + dj) % 5].y, acc1[2].y);
                acc1[2].z = fmaf(a.z, v[(2 + dj) % 5].z, acc1[2].z);
                acc1[2].w = fmaf(a.z, v[(2 + dj) % 5].w, acc1[2].w);
                acc1[3].x = fmaf(a.w, v[(3 + dj) % 5].x, acc1[3].x);
                acc1[3].y = fmaf(a.w, v[(3 + dj) % 5].y, acc1[3].y);
                acc1[3].z = fmaf(a.w, v[(3 + dj) % 5].z, acc1[3].z);
                acc1[3].w = fmaf(a.w, v[(3 + dj) % 5].w, acc1[3].w);
            }
        }
    }

    // ---------- Epilogue: += attn[25]*current, direct coalesced float4 ----------
    const float* curb = curv + (size_t)b * H * W * BINS;
    float*       outb = out  + (size_t)b * H * W * BINS;
    #pragma unroll
    for (int rr = 0; rr < 2; ++rr) {
        float4 a25 = *reinterpret_cast<const float4*>(
            s_attn + 25 * AS + (r0 + rr) * TW + c0);
        const float* ap = &a25.x;
        float4* accp = (rr == 0) ? acc0 : acc1;
        #pragma unroll
        for (int p = 0; p < 4; ++p) {
            int gaddr = ((h0 + r0 + rr) * W + (w0 + c0 + p)) * BINS + bg * 4;
            float4 cv = *reinterpret_cast<const float4*>(curb + gaddr);
            float a = ap[p];
            float4 o;
            o.x = fmaf(a, cv.x, accp[p].x);
            o.y = fmaf(a, cv.y, accp[p].y);
            o.z = fmaf(a, cv.z, accp[p].z);
            o.w = fmaf(a, cv.w, accp[p].w);
            *reinterpret_cast<float4*>(outb + gaddr) = o;
        }
    }
}

extern "C" void kernel_launch(void* const* d_in, const int* in_sizes, int n_in,
                              void* d_out, int out_size) {
    const float* attn = (const float*)d_in[0];   // [4,128,128,26]
    const float* refv = (const float*)d_in[1];   // [4,128,128,64]
    const float* curv = (const float*)d_in[2];   // [4,128,128,64]
    float* out = (float*)d_out;                  // [4,128,128,64]

    cudaFuncSetAttribute(agg_kernel, cudaFuncAttributeMaxDynamicSharedMemorySize,
                         SMEM_BYTES);

    const int nblocks = B * (H / TH) * (W / TW);   // 4*16*8 = 512
    agg_kernel<<<nblocks, THREADS, SMEM_BYTES>>>(attn, refv, curv, out);
}

// round 15
// speedup vs baseline: 1.2786x; 1.0173x over previous
#include <cuda_runtime.h>
#include <cstdint>

// Problem constants
#define B 4
#define H 128
#define W 128
#define BINS 64
#define KK 26            // 25 neighbors + current
#define KS 5

// Tiling: 8 x 16 output pixels per CTA, halo 2 -> 12 x 20 staged pixels
#define TH 8
#define TW 16
#define PH (TH + 4)      // 12
#define PW (TW + 4)      // 20
#define NPIX (PH * PW)   // 240 staged pixels
#define AS 132           // attn k-stride in floats (k*AS 16B-aligned)
#define THREADS 256

#define SREF_FLOATS (NPIX * BINS)      // 15360 -> 61440 B (natural [pix][bin])
#define SATTN_FLOATS (KK * AS)         // 3432  -> 13728 B
// + 16 bytes for the mbarrier (8B used, 8B pad)
#define SMEM_BYTES ((SREF_FLOATS + SATTN_FLOATS) * 4 + 16)   // 75184 B -> 3 CTAs/SM

__device__ __forceinline__ void mbar_init(uint32_t mbar, uint32_t cnt) {
    asm volatile("mbarrier.init.shared.b64 [%0], %1;" :: "r"(mbar), "r"(cnt) : "memory");
}
__device__ __forceinline__ void mbar_expect_tx(uint32_t mbar, uint32_t bytes) {
    asm volatile("mbarrier.arrive.expect_tx.shared.b64 _, [%0], %1;"
                 :: "r"(mbar), "r"(bytes) : "memory");
}
__device__ __forceinline__ void bulk_g2s(uint32_t dst, const void* src,
                                         uint32_t bytes, uint32_t mbar) {
    asm volatile(
        "cp.async.bulk.shared::cta.global.mbarrier::complete_tx::bytes "
        "[%0], [%1], %2, [%3];"
        :: "r"(dst), "l"(src), "r"(bytes), "r"(mbar) : "memory");
}
__device__ __forceinline__ void mbar_wait_p0(uint32_t mbar) {
    asm volatile(
        "{\n\t"
        ".reg .pred P;\n\t"
        "WAIT_%=:\n\t"
        "mbarrier.try_wait.parity.acquire.cta.shared::cta.b64 P, [%0], 0, 0x989680;\n\t"
        "@P bra DONE_%=;\n\t"
        "bra WAIT_%=;\n\t"
        "DONE_%=:\n\t"
        "}"
        :: "r"(mbar) : "memory");
}

__global__ __launch_bounds__(THREADS, 3)
void agg_kernel(const float* __restrict__ attn,
                const float* __restrict__ refv,
                const float* __restrict__ curv,
                float* __restrict__ out) {
    extern __shared__ float smem[];
    float* s_ref  = smem;                 // [pix][64 bins], pix = lr*PW + lc
    float* s_attn = smem + SREF_FLOATS;   // [k][pix], pix = r*TW + c

    const int tid  = threadIdx.x;
    const int bidx = blockIdx.x;          // 512 blocks: 8 tw x 16 th x 4 batch
    const int tw = bidx & 7;
    const int th = (bidx >> 3) & 15;
    const int b  = bidx >> 7;
    const int h0 = th * TH;
    const int w0 = tw * TW;

    const float* refb = refv + (size_t)b * H * W * BINS;
    const uint32_t s_ref_b = (uint32_t)__cvta_generic_to_shared(s_ref);
    const uint32_t mbar = (uint32_t)__cvta_generic_to_shared(
        smem + SREF_FLOATS + SATTN_FLOATS);

    if (tid == 0) mbar_init(mbar, 1);

    // Edge CTAs: pre-zero the whole ref buffer so clamped halo reads see 0.
    const bool edge = (tw == 0) | (tw == 7) | (th == 0) | (th == 15);
    if (edge) {
        float4 z = make_float4(0.f, 0.f, 0.f, 0.f);
        #pragma unroll
        for (int i = 0; i < SREF_FLOATS / 4 / THREADS; ++i)   // 15 iters
            reinterpret_cast<float4*>(s_ref)[tid + i * THREADS] = z;
    }
    __syncthreads();   // mbar init + zeros visible

    // One thread issues bulk row copies: each valid image row slice is a
    // contiguous [ncols x 64 floats] chunk in gmem.
    if (tid == 0) {
        asm volatile("fence.proxy.async.shared::cta;" ::: "memory");
        int cw_lo = w0 - 2; if (cw_lo < 0) cw_lo = 0;
        int cw_hi = w0 + TW + 1; if (cw_hi > W - 1) cw_hi = W - 1;
        int rh_lo = h0 - 2; if (rh_lo < 0) rh_lo = 0;
        int rh_hi = h0 + TH + 1; if (rh_hi > H - 1) rh_hi = H - 1;
        const uint32_t row_bytes = (uint32_t)(cw_hi - cw_lo + 1) * (BINS * 4);
        const int lc_lo = cw_lo - (w0 - 2);
        mbar_expect_tx(mbar, (uint32_t)(rh_hi - rh_lo + 1) * row_bytes);
        #pragma unroll 1
        for (int gh = rh_lo; gh <= rh_hi; ++gh) {
            int lr = gh - (h0 - 2);
            uint32_t dst = s_ref_b + (uint32_t)((lr * PW + lc_lo) * (BINS * 4));
            const float* src = refb + ((size_t)gh * W + cw_lo) * BINS;
            bulk_g2s(dst, src, row_bytes, mbar);
        }
    }

    // ---------- Stage attn, transposed [k][pix], division-free walker ----------
    {
        int pix = tid / KK;
        int k   = tid - pix * KK;
        #pragma unroll
        for (int i = 0; i < 13; ++i) {   // 3328 = 13*256 exactly
            int rr = pix >> 4, cc = pix & 15;
            float a = attn[(((b * H + h0 + rr) * W) + (w0 + cc)) * KK + k];
            s_attn[k * AS + pix] = a;
            k += 22; pix += 9;
            if (k >= KK) { k -= KK; pix += 1; }
        }
    }

    __syncthreads();        // attn STS visible to all
    mbar_wait_p0(mbar);     // ref bulk copies complete (acquire)

    // ---------- Compute: thread = 2 rows x 4 px x 4 bins (R7 body) ----------
    const int bg = tid & 15;             // float4 bin group 0..15
    const int pg = tid >> 4;             // 0..15
    const int r0 = (pg >> 2) * 2;        // first output row: 0,2,4,6
    const int c0 = (pg & 3) * 4;         // first output col: 0,4,8,12

    float4 acc0[4], acc1[4];
    #pragma unroll
    for (int p = 0; p < 4; ++p) {
        acc0[p] = make_float4(0.f, 0.f, 0.f, 0.f);
        acc1[p] = make_float4(0.f, 0.f, 0.f, 0.f);
    }

    const float* arow0 = s_attn + r0 * TW + c0;   // attn base, output row r0
    const float* arow1 = arow0 + TW;              // output row r0+1

    // Staged rows r0 .. r0+5: row (r0+arl) serves out-row r0 (di=arl, arl<=4)
    // and out-row r0+1 (di=arl-1, arl>=1) -> 2x vertical reuse of v window.
    // Rolling 5-slot window: col j lives in slot j%5; prefetch 4 cols ahead.
    #pragma unroll
    for (int arl = 0; arl < 6; ++arl) {
        const float* vrow = s_ref + ((r0 + arl) * PW + c0) * BINS + bg * 4;
        float4 v[5];
        #pragma unroll
        for (int j = 0; j < 4; ++j)
            v[j] = *reinterpret_cast<const float4*>(vrow + j * BINS);

        #pragma unroll
        for (int dj = 0; dj < 5; ++dj) {
            if (dj < 4)   // prefetch col dj+4 into dead slot; used 4 iters later
                v[(dj + 4) % 5] = *reinterpret_cast<const float4*>(vrow + (dj + 4) * BINS);
            if (arl <= 4) {   // compile-time pruned
                float4 a = *reinterpret_cast<const float4*>(arow0 + (arl * KS + dj) * AS);
                acc0[0].x = fmaf(a.x, v[(0 + dj) % 5].x, acc0[0].x);
                acc0[0].y = fmaf(a.x, v[(0 + dj) % 5].y, acc0[0].y);
                acc0[0].z = fmaf(a.x, v[(0 + dj) % 5].z, acc0[0].z);
                acc0[0].w = fmaf(a.x, v[(0 + dj) % 5].w, acc0[0].w);
                acc0[1].x = fmaf(a.y, v[(1 + dj) % 5].x, acc0[1].x);
                acc0[1].y = fmaf(a.y, v[(1 + dj) % 5].y, acc0[1].y);
                acc0[1].z = fmaf(a.y, v[(1 + dj) % 5].z, acc0[1].z);
                acc0[1].w = fmaf(a.y, v[(1 + dj) % 5].w, acc0[1].w);
                acc0[2].x = fmaf(a.z, v[(2 + dj) % 5].x, acc0[2].x);
                acc0[2].y = fmaf(a.z, v[(2 + dj) % 5].y, acc0[2].y);
                acc0[2].z = fmaf(a.z, v[(2 + dj) % 5].z, acc0[2].z);
                acc0[2].w = fmaf(a.z, v[(2 + dj) % 5].w, acc0[2].w);
                acc0[3].x = fmaf(a.w, v[(3 + dj) % 5].x, acc0[3].x);
                acc0[3].y = fmaf(a.w, v[(3 + dj) % 5].y, acc0[3].y);
                acc0[3].z = fmaf(a.w, v[(3 + dj) % 5].z, acc0[3].z);
                acc0[3].w = fmaf(a.w, v[(3 + dj) % 5].w, acc0[3].w);
            }
            if (arl >= 1) {   // compile-time pruned
                float4 a = *reinterpret_cast<const float4*>(arow1 + ((arl - 1) * KS + dj) * AS);
                acc1[0].x = fmaf(a.x, v[(0 + dj) % 5].x, acc1[0].x);
                acc1[0].y = fmaf(a.x, v[(0 + dj) % 5].y, acc1[0].y);
                acc1[0].z = fmaf(a.x, v[(0 + dj) % 5].z, acc1[0].z);
                acc1[0].w = fmaf(a.x, v[(0 + dj) % 5].w, acc1[0].w);
                acc1[1].x = fmaf(a.y, v[(1 + dj) % 5].x, acc1[1].x);
                acc1[1].y = fmaf(a.y, v[(1 + dj) % 5].y, acc1[1].y);
                acc1[1].z = fmaf(a.y, v[(1 + dj) % 5].z, acc1[1].z);
                acc1[1].w = fmaf(a.y, v[(1 + dj) % 5].w, acc1[1].w);
                acc1[2].x = fmaf(a.z, v[(2 + dj) % 5].x, acc1[2].x);
                acc1[2].y = fmaf(a.z, v[(2 + dj) % 5].y, acc1[2].y);
                acc1[2].z = fmaf(a.z, v[(2 + dj) % 5].z, acc1[2].z);
                acc1[2].w = fmaf(a.z, v[(2 + dj) % 5].w, acc1[2].w);
                acc1[3].x = fmaf(a.w, v[(3 + dj) % 5].x, acc1[3].x);
                acc1[3].y = fmaf(a.w, v[(3 + dj) % 5].y, acc1[3].y);
                acc1[3].z = fmaf(a.w, v[(3 + dj) % 5].z, acc1[3].z);
                acc1[3].w = fmaf(a.w, v[(3 + dj) % 5].w, acc1[3].w);
            }
        }
    }

    // ---------- Epilogue: += attn[25]*current, direct coalesced float4 ----------
    const float* curb = curv + (size_t)b * H * W * BINS;
    float*       outb = out  + (size_t)b * H * W * BINS;
    #pragma unroll
    for (int rr = 0; rr < 2; ++rr) {
        float4 a25 = *reinterpret_cast<const float4*>(
            s_attn + 25 * AS + (r0 + rr) * TW + c0);
        const float* ap = &a25.x;
        float4* accp = (rr == 0) ? acc0 : acc1;
        #pragma unroll
        for (int p = 0; p < 4; ++p) {
            int gaddr = ((h0 + r0 + rr) * W + (w0 + c0 + p)) * BINS + bg * 4;
            float4 cv = *reinterpret_cast<const float4*>(curb + gaddr);
            float a = ap[p];
            float4 o;
            o.x = fmaf(a, cv.x, accp[p].x);
            o.y = fmaf(a, cv.y, accp[p].y);
            o.z = fmaf(a, cv.z, accp[p].z);
            o.w = fmaf(a, cv.w, accp[p].w);
            *reinterpret_cast<float4*>(outb + gaddr) = o;
        }
    }
}

extern "C" void kernel_launch(void* const* d_in, const int* in_sizes, int n_in,
                              void* d_out, int out_size) {
    const float* attn = (const float*)d_in[0];   // [4,128,128,26]
    const float* refv = (const float*)d_in[1];   // [4,128,128,64]
    const float* curv = (const float*)d_in[2];   // [4,128,128,64]
    float* out = (float*)d_out;                  // [4,128,128,64]

    cudaFuncSetAttribute(agg_kernel, cudaFuncAttributeMaxDynamicSharedMemorySize,
                         SMEM_BYTES);

    const int nblocks = B * (H / TH) * (W / TW);   // 4*16*8 = 512
    agg_kernel<<<nblocks, THREADS, SMEM_BYTES>>>(attn, refv, curv, out);
}